// round 12
// baseline (speedup 1.0000x reference)
#include <cuda_runtime.h>
#include <cuda_fp16.h>
#include <cuda_fp8.h>
#include <cstdint>

#define DEV_INLINE __device__ __forceinline__

// ---------------------------------------------------------------------------
// Scratch (static device globals — allocation-free per harness rules)
// M=16384, K=4096, N=4096.
// ---------------------------------------------------------------------------
static __device__ __half g_A[(size_t)16384 * 4096];  // dequant x, fp16, [M,K]
static __device__ __half g_B[(size_t)4096 * 4096];   // dequant W, fp16, [K,N]

// ---------------------------------------------------------------------------
// Fused quantize + dequantize for BOTH tensors in one launch (R10, proven).
// Exact reference math; one fp16 rounding at the end.
// ---------------------------------------------------------------------------
__global__ void quant_both_kernel(const float* __restrict__ x,
                                  const float* __restrict__ w,
                                  __half* __restrict__ outX,
                                  __half* __restrict__ outW,
                                  int quadsX, int quadsTotal) {
    const int quad = (blockIdx.x * blockDim.x + threadIdx.x) >> 5;
    const int lane = threadIdx.x & 31;
    if (quad >= quadsTotal) return;

    const float* in;
    __half* out;
    size_t base;
    if (quad < quadsX) {
        in = x; out = outX; base = (size_t)quad * 512;
    } else {
        in = w; out = outW; base = (size_t)(quad - quadsX) * 512;
    }

    float4 v[4];
#pragma unroll
    for (int b = 0; b < 4; b++)
        v[b] = __ldcs(reinterpret_cast<const float4*>(in + base + b * 128) + lane);

    float am[4];
#pragma unroll
    for (int b = 0; b < 4; b++)
        am[b] = fmaxf(fmaxf(fabsf(v[b].x), fabsf(v[b].y)),
                      fmaxf(fabsf(v[b].z), fabsf(v[b].w)));
#pragma unroll
    for (int o = 16; o > 0; o >>= 1) {
#pragma unroll
        for (int b = 0; b < 4; b++)
            am[b] = fmaxf(am[b], __shfl_xor_sync(0xFFFFFFFFu, am[b], o));
    }

#pragma unroll
    for (int b = 0; b < 4; b++) {
        const float s = fmaxf(__fdiv_rn(am[b], 448.0f), 1e-12f);
        float f[4] = {v[b].x, v[b].y, v[b].z, v[b].w};
        __half h[4];
#pragma unroll
        for (int i = 0; i < 4; i++) {
            __nv_fp8_storage_t q =
                __nv_cvt_float_to_fp8(__fdiv_rn(f[i], s), __NV_SATFINITE, __NV_E4M3);
            __half_raw hr = __nv_cvt_fp8_to_halfraw(q, __NV_E4M3);
            h[i] = __float2half_rn(__half2float(__half(hr)) * s);
        }
        reinterpret_cast<uint2*>(out + base + b * 128)[lane] =
            *reinterpret_cast<const uint2*>(h);
    }
}

// ---------------------------------------------------------------------------
// mma.sync GEMM: C = A @ B + bias.
// R12: CTA tile 64x128x64 (acc 32 regs/thread), STAGES=2 (53.2KB smem),
// 3 CTAs/SM -> 24 warps/SM (6/SMSP) for latency hiding.
// 8 warps as 2(M)x4(N), warp tile 32x32. B-fragment ping-pong (proven R7).
// ---------------------------------------------------------------------------
static constexpr int BM = 64, BN = 128, BK = 64, STAGES = 2;
static constexpr int LDA = BK + 8;    // 72 halves (conflict-free ldsm)
static constexpr int LDB = BN + 8;    // 136 halves
static constexpr int A_STAGE = BM * LDA;          // 4608 halves
static constexpr int B_STAGE = BK * LDB;          // 8704 halves
static constexpr size_t SMEM_BYTES = (size_t)STAGES * (A_STAGE + B_STAGE) * 2;  // 53248

DEV_INLINE uint32_t smem_u32(const void* p) {
    return (uint32_t)__cvta_generic_to_shared(p);
}
DEV_INLINE void cp_async_16(uint32_t dst, const void* src) {
    asm volatile("cp.async.cg.shared.global [%0], [%1], 16;\n" :: "r"(dst), "l"(src));
}
DEV_INLINE void cp_commit() { asm volatile("cp.async.commit_group;\n"); }
template <int NN> DEV_INLINE void cp_wait() {
    asm volatile("cp.async.wait_group %0;\n" :: "n"(NN));
}
DEV_INLINE void ldsm_x4(uint32_t* r, uint32_t addr) {
    asm volatile("ldmatrix.sync.aligned.m8n8.x4.shared.b16 {%0,%1,%2,%3}, [%4];"
                 : "=r"(r[0]), "=r"(r[1]), "=r"(r[2]), "=r"(r[3]) : "r"(addr));
}
DEV_INLINE void ldsm_x4_t(uint32_t* r, uint32_t addr) {
    asm volatile("ldmatrix.sync.aligned.m8n8.x4.trans.shared.b16 {%0,%1,%2,%3}, [%4];"
                 : "=r"(r[0]), "=r"(r[1]), "=r"(r[2]), "=r"(r[3]) : "r"(addr));
}
DEV_INLINE void mma_16816(float* d, const uint32_t* a, const uint32_t* b) {
    asm volatile(
        "mma.sync.aligned.m16n8k16.row.col.f32.f16.f16.f32 "
        "{%0,%1,%2,%3}, {%4,%5,%6,%7}, {%8,%9}, {%0,%1,%2,%3};"
        : "+f"(d[0]), "+f"(d[1]), "+f"(d[2]), "+f"(d[3])
        : "r"(a[0]), "r"(a[1]), "r"(a[2]), "r"(a[3]), "r"(b[0]), "r"(b[1]));
}

__global__ void __launch_bounds__(256, 3)
gemm_mma_kernel(const __half* __restrict__ A, const __half* __restrict__ B,
                const float* __restrict__ bias, float* __restrict__ C,
                int M, int N, int K) {
    extern __shared__ __align__(128) __half smem[];
    __half* sA = smem;                          // [STAGES][BM][LDA]
    __half* sB = smem + STAGES * A_STAGE;       // [STAGES][BK][LDB]

    const int tid = threadIdx.x;
    const int lane = tid & 31;
    const int warp = tid >> 5;
    const int wm = (warp & 1) * 32;             // 2 warps along M (32 rows)
    const int wn = (warp >> 1) * 32;            // 4 warps along N (32 cols)

    // panel swizzle: 1024-CTA panels (32 bm x 32 bn); A band 16MB, B L2-resident
    const int linear = blockIdx.y * gridDim.x + blockIdx.x;  // grid=(32,256)
    const int bm = (linear >> 10) * 32 + (linear & 31);
    const int bn = (linear >> 5) & 31;

    const __half* Ab = A + (size_t)bm * BM * K;
    const __half* Bb = B + (size_t)bn * BN;

    const uint32_t sAu = smem_u32(sA);
    const uint32_t sBu = smem_u32(sB);

    // producer: A = 512 x 16B chunks (64 rows x 8), B = 1024 (64 rows x 16)
    auto issue = [&](int stage, int kt) {
        const int k0 = kt * BK;
        const uint32_t aBase = sAu + stage * A_STAGE * 2;
        const uint32_t bBase = sBu + stage * B_STAGE * 2;
#pragma unroll
        for (int t = 0; t < 2; t++) {
            int c = tid + t * 256;
            int row = c >> 3, ch = c & 7;
            cp_async_16(aBase + (row * LDA + ch * 8) * 2,
                        Ab + (size_t)row * K + k0 + ch * 8);
        }
#pragma unroll
        for (int t = 0; t < 4; t++) {
            int c = tid + t * 256;
            int row = c >> 4, ch = c & 15;
            cp_async_16(bBase + (row * LDB + ch * 8) * 2,
                        Bb + (size_t)(k0 + row) * N + ch * 8);
        }
        cp_commit();
    };

    float acc[2][4][4];
#pragma unroll
    for (int i = 0; i < 2; i++)
#pragma unroll
        for (int j = 0; j < 4; j++)
#pragma unroll
            for (int r = 0; r < 4; r++) acc[i][j][r] = 0.0f;

    const int KT = K / BK;
    issue(0, 0);

    // ldmatrix lane geometry (validated R4-R11)
    const int q = lane >> 3, r8 = lane & 7;
    const int aRow = r8 + (q & 1) * 8;
    const int aK8 = (q >> 1) * 8;
    const int bRow = r8 + (q & 1) * 8;
    const int bC8 = (q >> 1) * 8;

    for (int kt = 0; kt < KT; kt++) {
        cp_wait<0>();
        __syncthreads();   // all reads of the other buffer (kt-1) are done
        const int s = kt & 1;

        if (kt + 1 < KT) issue(s ^ 1, kt + 1);   // into buffer freed above
        else cp_commit();                        // uniform group accounting

        const uint32_t aSt = sAu + s * A_STAGE * 2;
        const uint32_t bSt = sBu + s * B_STAGE * 2;

        // B-fragment ping-pong: load B(kk+1) while MMAs consume B(kk)
        uint32_t rbb[2][4][2];
        auto loadB = [&](uint32_t (*rb)[2], int kk) {
#pragma unroll
            for (int p = 0; p < 2; p++) {
                uint32_t t4[4];
                ldsm_x4_t(t4, bSt + ((kk * 16 + bRow) * LDB + wn + p * 16 + bC8) * 2);
                rb[2 * p][0] = t4[0]; rb[2 * p][1] = t4[1];
                rb[2 * p + 1][0] = t4[2]; rb[2 * p + 1][1] = t4[3];
            }
        };
        loadB(rbb[0], 0);
#pragma unroll
        for (int kk = 0; kk < BK / 16; kk++) {
            uint32_t ra[2][4];
#pragma unroll
            for (int i = 0; i < 2; i++)
                ldsm_x4(ra[i], aSt + ((wm + i * 16 + aRow) * LDA + kk * 16 + aK8) * 2);
            if (kk < BK / 16 - 1) loadB(rbb[(kk + 1) & 1], kk + 1);
            uint32_t (*rb)[2] = rbb[kk & 1];
#pragma unroll
            for (int i = 0; i < 2; i++)
#pragma unroll
                for (int j = 0; j < 4; j++)
                    mma_16816(acc[i][j], ra[i], rb[j]);
        }
    }

    // epilogue: fused bias, direct stores
    const int gId = lane >> 2, tI = lane & 3;
#pragma unroll
    for (int i = 0; i < 2; i++) {
        const int row0 = bm * BM + wm + i * 16 + gId;
#pragma unroll
        for (int j = 0; j < 4; j++) {
            const int col = bn * BN + wn + j * 8 + tI * 2;
            const float bx = bias[col], by = bias[col + 1];
            float2 v0 = make_float2(acc[i][j][0] + bx, acc[i][j][1] + by);
            float2 v1 = make_float2(acc[i][j][2] + bx, acc[i][j][3] + by);
            *reinterpret_cast<float2*>(C + (size_t)row0 * N + col) = v0;
            *reinterpret_cast<float2*>(C + (size_t)(row0 + 8) * N + col) = v1;
        }
    }
}

// ---------------------------------------------------------------------------
// Launch
// ---------------------------------------------------------------------------
extern "C" void kernel_launch(void* const* d_in, const int* in_sizes, int n_in,
                              void* d_out, int out_size) {
    const float* x    = (const float*)d_in[0];   // [M, K]
    const float* w    = (const float*)d_in[1];   // [K, N]
    const float* bias = (const float*)d_in[2];   // [N]

    const int N = in_sizes[2];
    const int K = in_sizes[1] / N;
    const int M = in_sizes[0] / K;

    __half* gA = nullptr;
    __half* gB = nullptr;
    cudaGetSymbolAddress((void**)&gA, g_A);
    cudaGetSymbolAddress((void**)&gB, g_B);

    {   // single fused quant+dequant launch for x AND W
        int quadsX = in_sizes[0] / 512;
        int quadsW = in_sizes[1] / 512;
        int quadsTotal = quadsX + quadsW;
        quant_both_kernel<<<(quadsTotal + 7) / 8, 256>>>(x, w, gA, gB,
                                                         quadsX, quadsTotal);
    }
    {   // GEMM + fused bias
        static bool attr_set = false;
        if (!attr_set) {
            cudaFuncSetAttribute(gemm_mma_kernel,
                                 cudaFuncAttributeMaxDynamicSharedMemorySize,
                                 (int)SMEM_BYTES);
            attr_set = true;
        }
        dim3 grid(N / BN, M / BM);   // (32, 256) -> panel swizzle inside
        gemm_mma_kernel<<<grid, 256, SMEM_BYTES>>>(gA, gB, bias, (float*)d_out,
                                                   M, N, K);
    }
}

// round 13
// speedup vs baseline: 1.2320x; 1.2320x over previous
#include <cuda_runtime.h>
#include <cuda_fp16.h>
#include <cuda_fp8.h>
#include <cstdint>

#define DEV_INLINE __device__ __forceinline__

// ---------------------------------------------------------------------------
// Scratch (static device globals — allocation-free per harness rules)
// M=16384, K=4096, N=4096.
// ---------------------------------------------------------------------------
static __device__ __half g_A[(size_t)16384 * 4096];  // dequant x, fp16, [M,K]
static __device__ __half g_B[(size_t)4096 * 4096];   // dequant W, fp16, [K,N]

// ---------------------------------------------------------------------------
// Fused quantize + dequantize for BOTH tensors in one launch (R10, proven).
// Exact reference math; one fp16 rounding at the end.
// ---------------------------------------------------------------------------
__global__ void quant_both_kernel(const float* __restrict__ x,
                                  const float* __restrict__ w,
                                  __half* __restrict__ outX,
                                  __half* __restrict__ outW,
                                  int quadsX, int quadsTotal) {
    const int quad = (blockIdx.x * blockDim.x + threadIdx.x) >> 5;
    const int lane = threadIdx.x & 31;
    if (quad >= quadsTotal) return;

    const float* in;
    __half* out;
    size_t base;
    if (quad < quadsX) {
        in = x; out = outX; base = (size_t)quad * 512;
    } else {
        in = w; out = outW; base = (size_t)(quad - quadsX) * 512;
    }

    float4 v[4];
#pragma unroll
    for (int b = 0; b < 4; b++)
        v[b] = __ldcs(reinterpret_cast<const float4*>(in + base + b * 128) + lane);

    float am[4];
#pragma unroll
    for (int b = 0; b < 4; b++)
        am[b] = fmaxf(fmaxf(fabsf(v[b].x), fabsf(v[b].y)),
                      fmaxf(fabsf(v[b].z), fabsf(v[b].w)));
#pragma unroll
    for (int o = 16; o > 0; o >>= 1) {
#pragma unroll
        for (int b = 0; b < 4; b++)
            am[b] = fmaxf(am[b], __shfl_xor_sync(0xFFFFFFFFu, am[b], o));
    }

#pragma unroll
    for (int b = 0; b < 4; b++) {
        const float s = fmaxf(__fdiv_rn(am[b], 448.0f), 1e-12f);
        float f[4] = {v[b].x, v[b].y, v[b].z, v[b].w};
        __half h[4];
#pragma unroll
        for (int i = 0; i < 4; i++) {
            __nv_fp8_storage_t q =
                __nv_cvt_float_to_fp8(__fdiv_rn(f[i], s), __NV_SATFINITE, __NV_E4M3);
            __half_raw hr = __nv_cvt_fp8_to_halfraw(q, __NV_E4M3);
            h[i] = __float2half_rn(__half2float(__half(hr)) * s);
        }
        reinterpret_cast<uint2*>(out + base + b * 128)[lane] =
            *reinterpret_cast<const uint2*>(h);
    }
}

// ---------------------------------------------------------------------------
// mma.sync GEMM: C = A @ B + bias. CTA 128x128x64, 8 warps (2Mx4N),
// warp tile 64x32, 2 CTAs/SM, 3 stages.
// R13: mbarrier producer/consumer pipeline replaces __syncthreads lockstep —
// warps desynchronize up to ~1 stage so LDSM windows of one warp overlap
// HMMA streams of others (R10 showed tensor=64% with 36% lockstep bubbles).
// ---------------------------------------------------------------------------
static constexpr int BM = 128, BN = 128, BK = 64, STAGES = 3;
static constexpr int LDA = BK + 8;    // 72 halves (conflict-free ldsm)
static constexpr int LDB = BN + 8;    // 136 halves
static constexpr int A_STAGE_B = BM * LDA * 2;    // 18432 bytes
static constexpr int B_STAGE_B = BK * LDB * 2;    // 17408 bytes
static constexpr int SM_DATA = 128;               // data starts after barriers
static constexpr size_t SMEM_BYTES =
    SM_DATA + (size_t)STAGES * (A_STAGE_B + B_STAGE_B);   // 107648

DEV_INLINE uint32_t smem_u32(const void* p) {
    return (uint32_t)__cvta_generic_to_shared(p);
}
DEV_INLINE void cp_async_16(uint32_t dst, const void* src) {
    asm volatile("cp.async.cg.shared.global [%0], [%1], 16;\n" :: "r"(dst), "l"(src));
}
DEV_INLINE void ldsm_x4(uint32_t* r, uint32_t addr) {
    asm volatile("ldmatrix.sync.aligned.m8n8.x4.shared.b16 {%0,%1,%2,%3}, [%4];"
                 : "=r"(r[0]), "=r"(r[1]), "=r"(r[2]), "=r"(r[3]) : "r"(addr));
}
DEV_INLINE void ldsm_x4_t(uint32_t* r, uint32_t addr) {
    asm volatile("ldmatrix.sync.aligned.m8n8.x4.trans.shared.b16 {%0,%1,%2,%3}, [%4];"
                 : "=r"(r[0]), "=r"(r[1]), "=r"(r[2]), "=r"(r[3]) : "r"(addr));
}
DEV_INLINE void mma_16816(float* d, const uint32_t* a, const uint32_t* b) {
    asm volatile(
        "mma.sync.aligned.m16n8k16.row.col.f32.f16.f16.f32 "
        "{%0,%1,%2,%3}, {%4,%5,%6,%7}, {%8,%9}, {%0,%1,%2,%3};"
        : "+f"(d[0]), "+f"(d[1]), "+f"(d[2]), "+f"(d[3])
        : "r"(a[0]), "r"(a[1]), "r"(a[2]), "r"(a[3]), "r"(b[0]), "r"(b[1]));
}

#define MBAR_INIT(addr, count) \
    asm volatile("mbarrier.init.shared.b64 [%0], %1;" :: "r"(addr), "r"(count) : "memory")
#define MBAR_ARRIVE(addr) \
    asm volatile("mbarrier.arrive.shared.b64 _, [%0];" :: "r"(addr) : "memory")
#define CPASYNC_MBAR_ARRIVE(addr) \
    asm volatile("cp.async.mbarrier.arrive.noinc.shared::cta.b64 [%0];" :: "r"(addr) : "memory")
#define MBAR_WAIT_PARITY(addr, parity) do {                                             \
    uint32_t _m = (addr); uint32_t _p = (parity); uint32_t _d;                          \
    asm volatile(                                                                       \
        "{\n\t.reg .pred p;\n\t"                                                        \
        "mbarrier.try_wait.parity.acquire.cta.shared::cta.b64 p, [%1], %2;\n\t"         \
        "selp.b32 %0, 1, 0, p;\n\t}"                                                    \
        : "=r"(_d) : "r"(_m), "r"(_p) : "memory");                                      \
    if (!_d) {                                                                          \
        asm volatile(                                                                   \
            "{\n\t.reg .pred P1;\n\t"                                                   \
            "W_%=:\n\t"                                                                 \
            "mbarrier.try_wait.parity.acquire.cta.shared::cta.b64 P1, [%0], %1, 0x989680;\n\t" \
            "@P1 bra.uni D_%=;\n\t"                                                     \
            "bra.uni W_%=;\n\t"                                                         \
            "D_%=:\n\t}"                                                                \
            :: "r"(_m), "r"(_p) : "memory");                                            \
    }                                                                                   \
} while (0)

__global__ void __launch_bounds__(256, 2)
gemm_mma_kernel(const __half* __restrict__ A, const __half* __restrict__ B,
                const float* __restrict__ bias, float* __restrict__ C,
                int M, int N, int K) {
    extern __shared__ __align__(128) char smem[];
    const uint32_t sb = smem_u32(smem);
    const uint32_t FULL = sb;          // 3 x 8B
    const uint32_t EMPTY = sb + 24;    // 3 x 8B
    const uint32_t aData = sb + SM_DATA;
    const uint32_t bData = aData + STAGES * A_STAGE_B;

    const int tid = threadIdx.x;
    const int lane = tid & 31;
    const int warp = tid >> 5;
    const int wm = (warp & 1) * 64;
    const int wn = (warp >> 1) * 32;

    // panel swizzle: 512-CTA panels (16 bm x 32 bn)
    const int linear = blockIdx.y * gridDim.x + blockIdx.x;  // grid=(32,128)
    const int bm = (linear >> 9) * 16 + (linear & 15);
    const int bn = (linear >> 4) & 31;

    const __half* Ab = A + (size_t)bm * BM * K;
    const __half* Bb = B + (size_t)bn * BN;

    if (tid < STAGES) {
        MBAR_INIT(FULL + tid * 8, 256);   // one async-arrive per thread
        MBAR_INIT(EMPTY + tid * 8, 8);    // one arrive per warp
    }
    __syncthreads();

    // producer: A = 1024 x 16B chunks, B = 1024; async-arrive on full[stage]
    auto issue = [&](int stage, int kt) {
        const int k0 = kt * BK;
        const uint32_t aBase = aData + stage * A_STAGE_B;
        const uint32_t bBase = bData + stage * B_STAGE_B;
#pragma unroll
        for (int t = 0; t < 4; t++) {
            int c = tid + t * 256;
            int row = c >> 3, ch = c & 7;
            cp_async_16(aBase + (row * LDA + ch * 8) * 2,
                        Ab + (size_t)row * K + k0 + ch * 8);
        }
#pragma unroll
        for (int t = 0; t < 4; t++) {
            int c = tid + t * 256;
            int row = c >> 4, ch = c & 15;
            cp_async_16(bBase + (row * LDB + ch * 8) * 2,
                        Bb + (size_t)(k0 + row) * N + ch * 8);
        }
        CPASYNC_MBAR_ARRIVE(FULL + stage * 8);
    };

    float acc[4][4][4];
#pragma unroll
    for (int i = 0; i < 4; i++)
#pragma unroll
        for (int j = 0; j < 4; j++)
#pragma unroll
            for (int r = 0; r < 4; r++) acc[i][j][r] = 0.0f;

    const int KT = K / BK;   // 64 (>= STAGES)
#pragma unroll
    for (int p = 0; p < STAGES; p++) issue(p, p);

    // ldmatrix lane geometry (validated R4-R12)
    const int q = lane >> 3, r8 = lane & 7;
    const int aRow = r8 + (q & 1) * 8;
    const int aK8 = (q >> 1) * 8;
    const int bRow = r8 + (q & 1) * 8;
    const int bC8 = (q >> 1) * 8;

    int s = 0, ph = 0;   // stage index and parity = (kt/3)&1
    for (int kt = 0; kt < KT; kt++) {
        MBAR_WAIT_PARITY(FULL + s * 8, ph);

        const uint32_t aSt = aData + s * A_STAGE_B;
        const uint32_t bSt = bData + s * B_STAGE_B;
#pragma unroll
        for (int kk = 0; kk < BK / 16; kk++) {
            uint32_t ra[4][4], rb[4][2];
#pragma unroll
            for (int i = 0; i < 4; i++)
                ldsm_x4(ra[i], aSt + ((wm + i * 16 + aRow) * LDA + kk * 16 + aK8) * 2);
#pragma unroll
            for (int p = 0; p < 2; p++) {
                uint32_t t4[4];
                ldsm_x4_t(t4, bSt + ((kk * 16 + bRow) * LDB + wn + p * 16 + bC8) * 2);
                rb[2 * p][0] = t4[0]; rb[2 * p][1] = t4[1];
                rb[2 * p + 1][0] = t4[2]; rb[2 * p + 1][1] = t4[3];
            }
#pragma unroll
            for (int i = 0; i < 4; i++)
#pragma unroll
                for (int j = 0; j < 4; j++)
                    mma_16816(acc[i][j], ra[i], rb[j]);
        }

        // all fragment regs consumed by the MMAs above -> LDSMs complete;
        // this warp is done reading stage s
        if (lane == 0) MBAR_ARRIVE(EMPTY + s * 8);

        // refill stage s for kt+3 once all 8 warps are done reading it
        if (kt + STAGES < KT) {
            MBAR_WAIT_PARITY(EMPTY + s * 8, ph);
            issue(s, kt + STAGES);
        }

        if (++s == STAGES) { s = 0; ph ^= 1; }
    }

    // epilogue: fused bias, direct stores (registers only, no smem)
    const int gId = lane >> 2, tI = lane & 3;
#pragma unroll
    for (int i = 0; i < 4; i++) {
        const int row0 = bm * BM + wm + i * 16 + gId;
#pragma unroll
        for (int j = 0; j < 4; j++) {
            const int col = bn * BN + wn + j * 8 + tI * 2;
            const float bx = bias[col], by = bias[col + 1];
            float2 v0 = make_float2(acc[i][j][0] + bx, acc[i][j][1] + by);
            float2 v1 = make_float2(acc[i][j][2] + bx, acc[i][j][3] + by);
            *reinterpret_cast<float2*>(C + (size_t)row0 * N + col) = v0;
            *reinterpret_cast<float2*>(C + (size_t)(row0 + 8) * N + col) = v1;
        }
    }
}

// ---------------------------------------------------------------------------
// Launch
// ---------------------------------------------------------------------------
extern "C" void kernel_launch(void* const* d_in, const int* in_sizes, int n_in,
                              void* d_out, int out_size) {
    const float* x    = (const float*)d_in[0];   // [M, K]
    const float* w    = (const float*)d_in[1];   // [K, N]
    const float* bias = (const float*)d_in[2];   // [N]

    const int N = in_sizes[2];
    const int K = in_sizes[1] / N;
    const int M = in_sizes[0] / K;

    __half* gA = nullptr;
    __half* gB = nullptr;
    cudaGetSymbolAddress((void**)&gA, g_A);
    cudaGetSymbolAddress((void**)&gB, g_B);

    {   // single fused quant+dequant launch for x AND W
        int quadsX = in_sizes[0] / 512;
        int quadsW = in_sizes[1] / 512;
        int quadsTotal = quadsX + quadsW;
        quant_both_kernel<<<(quadsTotal + 7) / 8, 256>>>(x, w, gA, gB,
                                                         quadsX, quadsTotal);
    }
    {   // GEMM + fused bias (mbarrier pipeline)
        static bool attr_set = false;
        if (!attr_set) {
            cudaFuncSetAttribute(gemm_mma_kernel,
                                 cudaFuncAttributeMaxDynamicSharedMemorySize,
                                 (int)SMEM_BYTES);
            attr_set = true;
        }
        dim3 grid(N / BN, M / BM);   // (32, 128) -> panel swizzle inside
        gemm_mma_kernel<<<grid, 256, SMEM_BYTES>>>(gA, gB, bias, (float*)d_out,
                                                   M, N, K);
    }
}